// round 5
// baseline (speedup 1.0000x reference)
#include <cuda_runtime.h>
#include <math.h>

#define TT 8192
#define KK 1024
#define DD 1024
#define NTH 1024
#define START_TAG 1022
#define STOP_TAG 1023
#define NEGV (-10000.0f)
#define LOG2E 1.4426950408889634f
#define LN2F 0.6931471805599453f
#define FDEPTH 8

// ---------------- device scratch (no allocs allowed) ----------------
__device__ unsigned long long g_fvE[2][KK];       // (epoch<<32) | fv_bits, double-buffered
__device__ float g_gate[TT + 1];
__device__ float g_uc[TT], g_vc[TT], g_uu[TT], g_vu[TT];

__device__ __forceinline__ float ex2f(float x) {
    float y; asm("ex2.approx.f32 %0, %1;" : "=f"(y) : "f"(x)); return y;
}
__device__ __forceinline__ float lg2f(float x) {
    float y; asm("lg2.approx.f32 %0, %1;" : "=f"(y) : "f"(x)); return y;
}
// inf-proof helpers: clamp exp2 arg; floor log2 input
__device__ __forceinline__ float ex2s(float x) { return ex2f(fminf(x, 126.0f)); }
__device__ __forceinline__ float lg2s(float v) { return lg2f(fmaxf(v, 1e-37f)); }

__device__ __forceinline__ unsigned long long ldcg_u64(const unsigned long long* p) {
    unsigned long long v;
    asm volatile("ld.global.cg.u64 %0, [%1];" : "=l"(v) : "l"(p) : "memory");
    return v;
}
__device__ __forceinline__ void stcg_u64(unsigned long long* p, unsigned long long v) {
    asm volatile("st.global.cg.u64 [%0], %1;" :: "l"(p), "l"(v) : "memory");
}
__device__ __forceinline__ void cp_async4(void* smem_dst, const void* gsrc) {
    unsigned s = (unsigned)__cvta_generic_to_shared(smem_dst);
    asm volatile("cp.async.ca.shared.global [%0], [%1], 4;" :: "r"(s), "l"(gsrc) : "memory");
}
__device__ __forceinline__ void cp_commit() {
    asm volatile("cp.async.commit_group;" ::: "memory");
}
__device__ __forceinline__ void cp_wait7() {
    asm volatile("cp.async.wait_group 7;" ::: "memory");
}

// ---------------- prep 1: per-row dots with gate weight halves ----------------
__global__ void prep_dots(const float* __restrict__ reps,
                          const float* __restrict__ wc,
                          const float* __restrict__ wu) {
    int t = blockIdx.x, tid = threadIdx.x;                 // 256 threads
    const float4 a  = ((const float4*)(reps + (size_t)t * DD))[tid];
    const float4 c0 = ((const float4*)wc)[tid];
    const float4 c1 = ((const float4*)wc)[tid + 256];
    const float4 u0 = ((const float4*)wu)[tid];
    const float4 u1 = ((const float4*)wu)[tid + 256];
    float v0 = a.x * c0.x + a.y * c0.y + a.z * c0.z + a.w * c0.w;
    float v1 = a.x * c1.x + a.y * c1.y + a.z * c1.z + a.w * c1.w;
    float v2 = a.x * u0.x + a.y * u0.y + a.z * u0.z + a.w * u0.w;
    float v3 = a.x * u1.x + a.y * u1.y + a.z * u1.z + a.w * u1.w;
    #pragma unroll
    for (int o = 16; o; o >>= 1) {
        v0 += __shfl_xor_sync(0xffffffffu, v0, o);
        v1 += __shfl_xor_sync(0xffffffffu, v1, o);
        v2 += __shfl_xor_sync(0xffffffffu, v2, o);
        v3 += __shfl_xor_sync(0xffffffffu, v3, o);
    }
    __shared__ float sm[8][4];
    int lane = tid & 31, w = tid >> 5;
    if (lane == 0) { sm[w][0] = v0; sm[w][1] = v1; sm[w][2] = v2; sm[w][3] = v3; }
    __syncthreads();
    if (tid == 0) {
        float t0 = 0, t1 = 0, t2 = 0, t3 = 0;
        for (int i = 0; i < 8; i++) { t0 += sm[i][0]; t1 += sm[i][1]; t2 += sm[i][2]; t3 += sm[i][3]; }
        g_uc[t] = t0; g_vc[t] = t1; g_uu[t] = t2; g_vu[t] = t3;
    }
}

// ---------------- prep 2: gates + fvE init (fused) ----------------
__global__ void prep_gi(const int* __restrict__ spk) {
    int t = blockIdx.x * blockDim.x + threadIdx.x;
    if (t < TT) {
        int pt = (t > 0) ? t - 1 : 0;
        bool use_change = (t > 0) && (spk[t] != 0);
        float x = use_change ? (g_uc[pt] + g_vc[t]) : (g_uu[pt] + g_vu[t]);
        g_gate[t] = 1.0f / (1.0f + expf(-x));
    } else if (t == TT) {
        float x = g_uu[TT - 1] + g_vu[TT - 1];
        g_gate[TT] = 1.0f / (1.0f + expf(-x));
    }
    if (t < KK) {
        float v0 = (t == START_TAG) ? 0.0f : NEGV * LOG2E;
        g_fvE[0][t] = (unsigned long long)__float_as_uint(v0);       // epoch 0
        g_fvE[1][t] = 0xFFFFFFFF00000000ULL;                         // sentinel epoch
    }
}

// ---------------- persistent CRF forward ----------------
__global__ void __launch_bounds__(NTH, 1)
crf_main(const float* __restrict__ feats,
         const float* __restrict__ ti,
         const float* __restrict__ ta,
         float* __restrict__ out) {
    const int G   = gridDim.x;
    const int g   = blockIdx.x;
    const int tid = threadIdx.x;
    const int lane = tid & 31;
    const int wid  = tid >> 5;
    const int lrow = tid >> 7;            // 0..7 : row index within CTA
    const int j0   = (tid & 127) << 3;    // 8 prev-tags per thread
    const int r0 = (g * KK) / G;
    const int r1 = ((g + 1) * KK) / G;
    const int R  = r1 - r0;               // rows per CTA (<= 8)
    const bool active = lrow < R;
    const int row = r0 + lrow;

    // pin matrix slice in registers, loaded straight from inputs (no scratch pass)
    float ta2r[8], df2r[8];
    if (active) {
        const float4* pa = (const float4*)(ta + (size_t)row * KK + j0);
        const float4* pi = (const float4*)(ti + (size_t)row * KK + j0);
        float4 a0 = pa[0], a1 = pa[1], i0 = pi[0], i1 = pi[1];
        ta2r[0]=a0.x*LOG2E; ta2r[1]=a0.y*LOG2E; ta2r[2]=a0.z*LOG2E; ta2r[3]=a0.w*LOG2E;
        ta2r[4]=a1.x*LOG2E; ta2r[5]=a1.y*LOG2E; ta2r[6]=a1.z*LOG2E; ta2r[7]=a1.w*LOG2E;
        df2r[0]=(i0.x-a0.x)*LOG2E; df2r[1]=(i0.y-a0.y)*LOG2E;
        df2r[2]=(i0.z-a0.z)*LOG2E; df2r[3]=(i0.w-a0.w)*LOG2E;
        df2r[4]=(i1.x-a1.x)*LOG2E; df2r[5]=(i1.y-a1.y)*LOG2E;
        df2r[6]=(i1.z-a1.z)*LOG2E; df2r[7]=(i1.w-a1.w)*LOG2E;
    } else {
        #pragma unroll
        for (int q = 0; q < 8; q++) { ta2r[q] = 0.0f; df2r[q] = 0.0f; }
    }

    __shared__ float s_gate[TT + 8];      // all gates resident in smem (32 KB)
    __shared__ __align__(16) float s_fvp[KK];
    __shared__ float s_feat[FDEPTH][8];   // cp.async ring of emission rows
    __shared__ float s_part[8][4];
    __shared__ float s_red[32];
    __shared__ float s_ref;
    __shared__ float s_m;

    // prologue: gates to smem
    for (int i = tid; i <= TT; i += NTH) s_gate[i] = g_gate[i];
    // prologue: prime the feats ring (8 groups, one per slot)
    if (wid == 5) {
        #pragma unroll
        for (int i = 0; i < FDEPTH; i++) {
            if (lane < R) cp_async4(&s_feat[i][lane], feats + (size_t)i * KK + r0 + lane);
            cp_commit();
        }
    }
    // each poller thread owns one publisher CTA's sentinel row (its last row)
    int srow = 0;
    if (tid < G) srow = ((tid + 1) * KK) / G - 1;
    __syncthreads();

    for (int t = 0; t < TT; ++t) {
        const int p = t & 1;
        const unsigned ee = (unsigned)t;

        // feats ring: retire slot t (issued 8 steps ago), issue slot t+8
        if (wid == 5) {
            cp_wait7();
            int tf = t + FDEPTH;
            if (lane < R && tf < TT)
                cp_async4(&s_feat[tf & (FDEPTH - 1)][lane], feats + (size_t)tf * KK + r0 + lane);
            cp_commit();
        }

        // sentinel poll: only G threads generate L2 traffic; 27 warps sleep at BAR
        if (tid < G) {
            unsigned long long pk = ldcg_u64(&g_fvE[p][srow]);
            while ((unsigned)(pk >> 32) != ee) {
                __nanosleep(32);
                pk = ldcg_u64(&g_fvE[p][srow]);
            }
            if (tid == 0) s_ref = t ? __uint_as_float((unsigned)pk) : 0.0f;
        }
        __syncthreads();                              // BAR1: all CTAs published
        const float ref  = s_ref;
        const float gate = s_gate[t];

        // bulk read + validate (rare retry: only store-visibility skew) + pre-shifted stage
        {
            unsigned long long pk = ldcg_u64(&g_fvE[p][tid]);
            while ((unsigned)(pk >> 32) != ee) pk = ldcg_u64(&g_fvE[p][tid]);
            s_fvp[tid] = __uint_as_float((unsigned)pk) - ref;
        }
        __syncthreads();                              // BAR2

        // inner compute: 8 EX2/thread; 3 FMA-pipe ops/elem (fadd+fma+fmin) -> MUFU-bound
        float acc = 0.0f;
        if (active) {
            float4 f0 = *(const float4*)&s_fvp[j0];
            float4 f1 = *(const float4*)&s_fvp[j0 + 4];
            float a = 0.0f, b = 0.0f;
            a += ex2s(f0.x + fmaf(gate, df2r[0], ta2r[0]));
            b += ex2s(f0.y + fmaf(gate, df2r[1], ta2r[1]));
            a += ex2s(f0.z + fmaf(gate, df2r[2], ta2r[2]));
            b += ex2s(f0.w + fmaf(gate, df2r[3], ta2r[3]));
            a += ex2s(f1.x + fmaf(gate, df2r[4], ta2r[4]));
            b += ex2s(f1.y + fmaf(gate, df2r[5], ta2r[5]));
            a += ex2s(f1.z + fmaf(gate, df2r[6], ta2r[6]));
            b += ex2s(f1.w + fmaf(gate, df2r[7], ta2r[7]));
            acc = a + b;
        }
        #pragma unroll
        for (int o = 16; o; o >>= 1) acc += __shfl_xor_sync(0xffffffffu, acc, o);
        if (lane == 0) s_part[lrow][wid & 3] = acc;
        __syncthreads();                              // BAR3

        // warp 0 finalizes all rows: combine partials, guarded log2, publish (epoch|value)
        if (wid == 0) {
            int rr = lane >> 2;
            float v = s_part[rr][lane & 3];
            v += __shfl_xor_sync(0xffffffffu, v, 1);
            v += __shfl_xor_sync(0xffffffffu, v, 2);
            if ((lane & 3) == 0 && rr < R) {
                float fvnew = ref + s_feat[t & (FDEPTH - 1)][rr] * LOG2E + lg2s(v);
                unsigned long long packed =
                    ((unsigned long long)(unsigned)(t + 1) << 32) | __float_as_uint(fvnew);
                stcg_u64(&g_fvE[p ^ 1][r0 + rr], packed);
            }
        }
        // no trailing sync: next-iter smem writes are ordered behind BAR1/BAR2,
        // which warp 0 joins only after finalize.
    }

    // ---------------- terminal: CTA owning STOP row ----------------
    if (g == G - 1) {
        const float gT = g_gate[TT];
        const bool mine = (lrow == R - 1);            // row == STOP_TAG
        float term[8];
        float lm = -3.0e38f;
        if (mine) {
            #pragma unroll
            for (int q = 0; q < 8; q++) {
                unsigned long long pk;
                do { pk = ldcg_u64(&g_fvE[0][j0 + q]); }         // TT even -> buffer 0
                while ((unsigned)(pk >> 32) != (unsigned)TT);
                float fvf = __uint_as_float((unsigned)pk);
                term[q] = fvf + fmaf(gT, df2r[q], ta2r[q]);
                lm = fmaxf(lm, term[q]);
            }
        }
        #pragma unroll
        for (int o = 16; o; o >>= 1) lm = fmaxf(lm, __shfl_xor_sync(0xffffffffu, lm, o));
        if (lane == 0) s_red[wid] = lm;
        __syncthreads();
        if (wid == 0) {
            float m = s_red[lane];
            #pragma unroll
            for (int o = 16; o; o >>= 1) m = fmaxf(m, __shfl_xor_sync(0xffffffffu, m, o));
            if (lane == 0) s_m = m;
        }
        __syncthreads();
        const float M = s_m;
        float s = 0.0f;
        if (mine) {
            #pragma unroll
            for (int q = 0; q < 8; q++) s += ex2s(term[q] - M);
        }
        #pragma unroll
        for (int o = 16; o; o >>= 1) s += __shfl_xor_sync(0xffffffffu, s, o);
        if (lane == 0) s_red[wid] = s;
        __syncthreads();
        if (tid == 0) {
            float tot = 0.0f;
            for (int w = 0; w < 32; w++) tot += s_red[w];
            out[0] = (M + lg2s(tot)) * LN2F;          // back to natural log
        }
    }
}

// ---------------- launch (3 kernels/call: ncu skip lands on crf_main) ----------------
extern "C" void kernel_launch(void* const* d_in, const int* in_sizes, int n_in,
                              void* d_out, int out_size) {
    const float* feats = (const float*)d_in[0];
    const float* reps  = (const float*)d_in[1];
    const float* wc    = (const float*)d_in[2];
    const float* wu    = (const float*)d_in[3];
    const float* ti    = (const float*)d_in[4];
    const float* ta    = (const float*)d_in[5];
    const int*   spk   = (const int*)d_in[6];

    int dev = 0; cudaGetDevice(&dev);
    int sm = 148;
    cudaDeviceGetAttribute(&sm, cudaDevAttrMultiProcessorCount, dev);
    int grid = sm;
    if (grid > 256) grid = 256;
    if (grid < 128) grid = 128;    // row mapping needs <=8 rows/CTA

    prep_dots<<<TT, 256>>>(reps, wc, wu);
    prep_gi<<<(TT + 1 + 1023) / 1024, 1024>>>(spk);
    crf_main<<<grid, NTH>>>(feats, ti, ta, (float*)d_out);
}